// round 5
// baseline (speedup 1.0000x reference)
#include <cuda_runtime.h>
#include <cuda_bf16.h>

#define E_EVENTS 1024
#define B_SAMPLES 256
#define DIN 784
#define DH 400
#define DOUT 10
#define SLOTS 32
#define NT_A 416

// Static device scratch (no cudaMalloc allowed)
__device__ float g_W1T[DIN * DH];            // [784][400]
__device__ float g_W2c[(DH + 4) * DOUT];     // [404][10], rows 400..403 = 0 (pad target)
__device__ unsigned short g_list[(size_t)B_SAMPLES * E_EVENTS * SLOTS]; // spike lists
__device__ unsigned short g_cnt[B_SAMPLES * E_EVENTS];                  // true counts
__device__ unsigned g_ovmask[(size_t)B_SAMPLES * E_EVENTS * 16];        // only on overflow

__global__ void prep_kernel(const float* __restrict__ W1,
                            const float* __restrict__ W2,
                            const float* __restrict__ b2) {
    int idx = blockIdx.x * blockDim.x + threadIdx.x;
    if (idx < DIN * DH) {
        int p = idx / DH;
        int j = idx - p * DH;
        g_W1T[idx] = W1[j * DIN + p];
    } else if (idx < DIN * DH + (DH + 4) * DOUT) {
        int i = idx - DIN * DH;
        int j = i / DOUT;
        int d = i - j * DOUT;
        g_W2c[i] = (j < DH)
            ? __fadd_rn(W2[d * DH + j], __fdiv_rn(b2[d], 400.0f))
            : 0.0f;   // pad rows: adding 0.0f is a no-op in the chain
    }
}

#define A_SMEM ((E_EVENTS + 1) * 8 + E_EVENTS * 13 * 4 + 32)

// Layer 1: one CTA per sample, 13 warps, no barriers in the main loop.
// Epilogue converts mask rows into ordered compact spike lists in global.
__global__ __launch_bounds__(NT_A, 2) void l1_kernel(
    const float* __restrict__ times,
    const int*   __restrict__ pix,
    const float* __restrict__ b1)
{
    extern __shared__ unsigned char dyn[];
    float2*   s_ev   = (float2*)dyn;                    // [1025] (decay1, p*1600 bits)
    unsigned* s_mask = (unsigned*)(s_ev + E_EVENTS + 1); // [1024][13]

    const float TAUF = 0.6213349345596119f;  // float(-1/ln(0.2))
    const int b    = blockIdx.x;
    const int tid  = threadIdx.x;
    const int warp = tid >> 5;
    const int lane = tid & 31;

    for (int e = tid; e < E_EVENTS; e += NT_A) {
        float t  = times[b * E_EVENTS + e];
        float tp = (e > 0) ? times[b * E_EVENTS + e - 1] : 0.0f;
        float d1 = expf(__fdiv_rn(-(t - tp), TAUF));
        int   p  = pix[b * E_EVENTS + e];
        s_ev[e] = make_float2(d1, __int_as_float(p * (DH * 4)));
    }
    if (tid == 0) s_ev[E_EVENTS] = make_float2(1.0f, __int_as_float(0));
    __syncthreads();

    float h1 = 0.0f;
    float bias1j = (tid < DH) ? __fdiv_rn(b1[tid], 784.0f) : 0.0f;
    const char* w1b = (const char*)g_W1T + tid * 4;

    float2 ev = s_ev[0];
    float wv = *(const float*)(w1b + __float_as_int(ev.y));

    #pragma unroll 8
    for (int e = 0; e < E_EVENTS; ++e) {
        float2 evn = s_ev[e + 1];
        float wnext = *(const float*)(w1b + __float_as_int(evn.y));

        h1 = __fadd_rn(__fadd_rn(__fmul_rn(h1, ev.x), wv), bias1j);
        bool fired = (tid < DH) && (h1 >= 0.5f);
        if (fired) h1 = 0.0f;
        unsigned m = __ballot_sync(0xffffffffu, fired);
        if (lane == 0) s_mask[e * 13 + warp] = m;

        ev = evn;
        wv = wnext;
    }
    __syncthreads();

    // Epilogue: each warp compacts a strided set of events into g_list.
    for (int e = warp; e < E_EVENTS; e += 13) {
        unsigned m = (lane < 13) ? s_mask[e * 13 + lane] : 0u;
        int c = __popc(m);
        int sc = c;
        #pragma unroll
        for (int d = 1; d < 32; d <<= 1) {
            int v = __shfl_up_sync(0xffffffffu, sc, d);
            if (lane >= d) sc += v;
        }
        int n = __shfl_sync(0xffffffffu, sc, 12);
        int pos = sc - c;
        size_t base = ((size_t)b * E_EVENTS + e) * SLOTS;
        unsigned mm = m;
        while (mm) {
            int bit = __ffs(mm) - 1;
            mm &= mm - 1;
            if (pos < SLOTS)
                g_list[base + pos] = (unsigned short)(lane * 32 + bit);
            ++pos;
        }
        if (lane == 0) {
            g_cnt[b * E_EVENTS + e] = (unsigned short)n;
            if (n <= SLOTS) {
                int np = (n + 3) & ~3;
                for (int i = n; i < np; ++i)
                    g_list[base + i] = (unsigned short)DH;  // zero-weight pad
            }
        }
        if (n > SLOTS && lane < 13)
            g_ovmask[((size_t)b * E_EVENTS + e) * 16 + lane] = m;
    }
}

// Layer 2: one warp per sample; lanes 0..9 = output-dim chains.
__global__ __launch_bounds__(32) void l2_kernel(
    const float* __restrict__ times,
    float*       __restrict__ out)
{
    __shared__ float s_d2[E_EVENTS];
    const float TAUF = 0.6213349345596119f;
    const int b    = blockIdx.x;
    const int lane = threadIdx.x;

    for (int e = lane; e < E_EVENTS; e += 32) {
        float t   = times[b * E_EVENTS + e];
        float tp  = (e > 0) ? times[b * E_EVENTS + e - 1] : 0.0f;
        float th  = __fadd_rn(t, 0.1f);
        float thp = (e > 0) ? __fadd_rn(tp, 0.1f) : 0.0f;
        s_d2[e] = expf(__fdiv_rn(-(th - thp), TAUF));
    }
    __syncwarp();

    if (lane < DOUT) {
        float h2 = 0.0f, cnt = 0.0f;
        const unsigned short* cn = g_cnt + b * E_EVENTS;
        for (int e = 0; e < E_EVENTS; ++e) {
            h2 = __fmul_rn(h2, s_d2[e]);
            int n = cn[e];
            size_t base = ((size_t)b * E_EVENTS + e) * SLOTS;
            if (n <= SLOTS) {
                int ng = (n + 3) >> 2;
                const ushort4* jp = (const ushort4*)(g_list + base);
                for (int g = 0; g < ng; ++g) {
                    ushort4 j4 = __ldg(jp + g);
                    float w0 = __ldg(g_W2c + j4.x * DOUT + lane);
                    float w1 = __ldg(g_W2c + j4.y * DOUT + lane);
                    float w2 = __ldg(g_W2c + j4.z * DOUT + lane);
                    float w3 = __ldg(g_W2c + j4.w * DOUT + lane);
                    h2 = __fadd_rn(h2, w0);
                    if (h2 >= 0.5f) { cnt += 1.0f; h2 = 0.0f; }
                    h2 = __fadd_rn(h2, w1);
                    if (h2 >= 0.5f) { cnt += 1.0f; h2 = 0.0f; }
                    h2 = __fadd_rn(h2, w2);
                    if (h2 >= 0.5f) { cnt += 1.0f; h2 = 0.0f; }
                    h2 = __fadd_rn(h2, w3);
                    if (h2 >= 0.5f) { cnt += 1.0f; h2 = 0.0f; }
                }
            } else {
                // rare overflow: scan mask row, ascending j
                const unsigned* mr = g_ovmask + ((size_t)b * E_EVENTS + e) * 16;
                for (int w = 0; w < 13; ++w) {
                    unsigned m = __ldg(mr + w);
                    while (m) {
                        int bit = __ffs(m) - 1;
                        m &= m - 1;
                        int j = w * 32 + bit;
                        h2 = __fadd_rn(h2, __ldg(g_W2c + j * DOUT + lane));
                        if (h2 >= 0.5f) { cnt += 1.0f; h2 = 0.0f; }
                    }
                }
            }
        }
        out[b * DOUT + lane] = __fdiv_rn(cnt, 64.0f);
    }
}

extern "C" void kernel_launch(void* const* d_in, const int* in_sizes, int n_in,
                              void* d_out, int out_size) {
    const float* times = (const float*)d_in[0];  // [256,1024] f32
    const int*   pixv  = (const int*)d_in[1];    // [256,1024] i32
    const float* W1    = (const float*)d_in[2];  // [400,784]
    const float* b1    = (const float*)d_in[3];  // [400]
    const float* W2    = (const float*)d_in[4];  // [10,400]
    const float* b2    = (const float*)d_in[5];  // [10]

    cudaFuncSetAttribute(l1_kernel,
                         cudaFuncAttributeMaxDynamicSharedMemorySize, A_SMEM);

    int prep_n = DIN * DH + (DH + 4) * DOUT;
    prep_kernel<<<(prep_n + 255) / 256, 256>>>(W1, W2, b2);
    l1_kernel<<<B_SAMPLES, NT_A, A_SMEM>>>(times, pixv, b1);
    l2_kernel<<<B_SAMPLES, 32>>>(times, (float*)d_out);
}

// round 6
// speedup vs baseline: 1.8818x; 1.8818x over previous
#include <cuda_runtime.h>
#include <cuda_bf16.h>

#define EE 1024
#define BB 256
#define DIN 784
#define DH 400
#define DOUT 10
#define NT_A 416
#define CAP_G 6144          // group capacity per sample (avg ~3200 expected)
#define RING_G 128          // groups per ring buffer (chunk avg ~61)
#define CEVT 32             // events per chunk
#define NCH (EE / CEVT)

// Static device scratch (no cudaMalloc allowed)
__device__ float g_W1T[DIN * DH + 32];          // transposed W1, padded
__device__ float g_W2p[DH * 12];                // W2 rows padded to 12 floats
__device__ float g_ws[(size_t)BB * CAP_G * 24]; // weight stream (groups of 2x12 floats)
__device__ unsigned short g_gc[BB * EE];        // groups per event
__device__ unsigned g_chk[BB][NCH + 1];         // per-chunk group prefix
__device__ unsigned g_tot[BB];                  // total groups per sample
__device__ unsigned g_maskov[BB][EE][13];       // masks (overflow fallback only)

__global__ void prep_kernel(const float* __restrict__ W1,
                            const float* __restrict__ W2,
                            const float* __restrict__ b2) {
    int idx = blockIdx.x * blockDim.x + threadIdx.x;
    if (idx < DIN * DH) {
        int p = idx / DH;
        int j = idx - p * DH;
        g_W1T[idx] = W1[j * DIN + p];
    } else if (idx < DIN * DH + DH * 12) {
        int i = idx - DIN * DH;
        int j = i / 12;
        int d = i - j * 12;
        g_W2p[i] = (d < DOUT)
            ? __fadd_rn(W2[d * DH + j], __fdiv_rn(b2[d], 400.0f))
            : 0.0f;
    }
}

#define A_SMEM ((EE + 1) * 8 + EE * 13 * 4 + EE * 4 * 2 + 32)

// Layer 1: one CTA/sample, 13 warps, no barriers in main loop.
// Epilogue: masks -> padded linear weight stream + group counts/prefixes.
__global__ __launch_bounds__(NT_A, 2) void l1_kernel(
    const float* __restrict__ times,
    const int*   __restrict__ pix,
    const float* __restrict__ b1)
{
    extern __shared__ unsigned char dyn[];
    float2*   s_ev   = (float2*)dyn;                       // [EE+1]
    unsigned* s_mask = (unsigned*)(s_ev + EE + 1);         // [EE][13]
    unsigned* s_g    = s_mask + EE * 13;                   // [EE] groups/event
    unsigned* s_goff = s_g + EE;                           // [EE] exclusive prefix
    unsigned* s_Gt   = s_goff + EE;                        // [1]

    const float TAUF = 0.6213349345596119f;  // float(-1/ln(0.2))
    const int b    = blockIdx.x;
    const int tid  = threadIdx.x;
    const int warp = tid >> 5;
    const int lane = tid & 31;

    for (int e = tid; e < EE; e += NT_A) {
        float t  = times[b * EE + e];
        float tp = (e > 0) ? times[b * EE + e - 1] : 0.0f;
        float d1 = expf(__fdiv_rn(-(t - tp), TAUF));
        int   p  = pix[b * EE + e];
        s_ev[e] = make_float2(d1, __int_as_float(p * (DH * 4)));
    }
    if (tid == 0) s_ev[EE] = make_float2(1.0f, __int_as_float(0));
    __syncthreads();

    float h1 = 0.0f;
    float bias1j = (tid < DH) ? __fdiv_rn(b1[tid], 784.0f) : 0.0f;
    const char* w1b = (const char*)g_W1T + tid * 4;

    float2 ev = s_ev[0];
    float wv = *(const float*)(w1b + __float_as_int(ev.y));

    #pragma unroll 8
    for (int e = 0; e < EE; ++e) {
        float2 evn = s_ev[e + 1];
        float wnext = *(const float*)(w1b + __float_as_int(evn.y));

        h1 = __fadd_rn(__fadd_rn(__fmul_rn(h1, ev.x), wv), bias1j);
        bool fired = (tid < DH) && (h1 >= 0.5f);
        if (fired) h1 = 0.0f;
        unsigned m = __ballot_sync(0xffffffffu, fired);
        if (lane == 0) s_mask[e * 13 + warp] = m;

        ev = evn;
        wv = wnext;
    }
    __syncthreads();

    // ---- epilogue ----
    // 1) groups per event
    for (int e = tid; e < EE; e += NT_A) {
        int n = 0;
        #pragma unroll
        for (int w = 0; w < 13; ++w) n += __popc(s_mask[e * 13 + w]);
        s_g[e] = (unsigned)((n + 1) >> 1);
    }
    __syncthreads();

    // 2) exclusive prefix scan over groups (warp 0)
    if (warp == 0) {
        unsigned run = 0;
        for (int c = 0; c < EE / 32; ++c) {
            unsigned v = s_g[c * 32 + lane];
            unsigned sc = v;
            #pragma unroll
            for (int d = 1; d < 32; d <<= 1) {
                unsigned u = __shfl_up_sync(0xffffffffu, sc, d);
                if (lane >= d) sc += u;
            }
            s_goff[c * 32 + lane] = run + sc - v;
            run += __shfl_sync(0xffffffffu, sc, 31);
        }
        if (lane == 0) *s_Gt = run;
    }
    __syncthreads();

    const unsigned G = *s_Gt;
    if (tid == 0) g_tot[b] = G;
    if (tid < NCH) g_chk[b][tid] = s_goff[tid * CEVT];
    if (tid == NCH) g_chk[b][NCH] = G;

    if (G > CAP_G) {
        // overflow (effectively never): publish masks, chain uses slow path
        for (int i = tid; i < EE * 13; i += NT_A)
            (&g_maskov[b][0][0])[i] = s_mask[i];
        return;
    }

    // 3) write padded weight stream; each warp a strided set of events
    for (int e = warp; e < EE; e += 13) {
        unsigned m = (lane < 13) ? s_mask[e * 13 + lane] : 0u;
        int c = __popc(m);
        int sc = c;
        #pragma unroll
        for (int d = 1; d < 32; d <<= 1) {
            int v = __shfl_up_sync(0xffffffffu, sc, d);
            if (lane >= d) sc += v;
        }
        int n   = __shfl_sync(0xffffffffu, sc, 31);     // spikes this event
        int pos = sc - c;                               // my first slot
        float* ebase = g_ws + (size_t)b * CAP_G * 24 + (size_t)s_goff[e] * 24;
        unsigned mm = m;
        while (mm) {
            int bit = __ffs(mm) - 1;
            mm &= mm - 1;
            int j = lane * 32 + bit;
            const float4* src = (const float4*)(g_W2p + j * 12);
            float4* dst = (float4*)(ebase + (size_t)pos * 12);
            dst[0] = __ldg(src);
            dst[1] = __ldg(src + 1);
            dst[2] = __ldg(src + 2);
            ++pos;
        }
        if ((n & 1) && lane == 0) {   // odd -> one zero pad entry
            float4 z = make_float4(0.f, 0.f, 0.f, 0.f);
            float4* dst = (float4*)(ebase + (size_t)n * 12);
            dst[0] = z; dst[1] = z; dst[2] = z;
        }
        if (lane == 0) g_gc[b * EE + e] = (unsigned short)s_g[e];
    }
}

__device__ __forceinline__ void cp_chunk(float* dst_sh, const float* src,
                                         int bytes, int lane) {
    unsigned sbase = (unsigned)__cvta_generic_to_shared(dst_sh);
    for (int off = lane * 16; off < bytes; off += 32 * 16)
        asm volatile("cp.async.ca.shared.global [%0], [%1], 16;"
                     :: "r"(sbase + off), "l"((const char*)src + off));
}

// Layer 2: one warp per sample; lanes 0..9 = output-dim chains.
// Weight stream double-buffered through shared via cp.async.
__global__ __launch_bounds__(32) void l2_kernel(
    const float* __restrict__ times,
    float*       __restrict__ out)
{
    __shared__ float s_d2[EE];
    __shared__ unsigned short s_gc[EE];
    __shared__ unsigned s_chk[NCH + 1];
    __shared__ __align__(16) float ring[2][RING_G * 24];

    const float TAUF = 0.6213349345596119f;
    const int b    = blockIdx.x;
    const int lane = threadIdx.x;

    for (int e = lane; e < EE; e += 32) {
        float t   = times[b * EE + e];
        float tp  = (e > 0) ? times[b * EE + e - 1] : 0.0f;
        float th  = __fadd_rn(t, 0.1f);
        float thp = (e > 0) ? __fadd_rn(tp, 0.1f) : 0.0f;
        s_d2[e] = expf(__fdiv_rn(-(th - thp), TAUF));
    }
    const unsigned tot = g_tot[b];
    for (int e = lane; e < EE; e += 32) s_gc[e] = g_gc[b * EE + e];
    for (int i = lane; i < NCH + 1; i += 32) s_chk[i] = g_chk[b][i];
    __syncwarp();

    float h2 = 0.0f, cnt = 0.0f;

    if (tot > CAP_G) {
        // slow fallback: scan masks directly
        if (lane < DOUT) {
            for (int e = 0; e < EE; ++e) {
                h2 = __fmul_rn(h2, s_d2[e]);
                for (int w = 0; w < 13; ++w) {
                    unsigned m = g_maskov[b][e][w];
                    while (m) {
                        int bit = __ffs(m) - 1;
                        m &= m - 1;
                        int j = w * 32 + bit;
                        h2 = __fadd_rn(h2, __ldg(g_W2p + j * 12 + lane));
                        if (h2 >= 0.5f) { cnt += 1.0f; h2 = 0.0f; }
                    }
                }
            }
            out[b * DOUT + lane] = __fdiv_rn(cnt, 64.0f);
        }
        return;
    }

    const float* ws = g_ws + (size_t)b * CAP_G * 24;

    // prefetch chunk 0
    {
        int gc0 = (int)(s_chk[1] - s_chk[0]);
        if (gc0 <= RING_G)
            cp_chunk(ring[0], ws + (size_t)s_chk[0] * 24, gc0 * 96, lane);
        asm volatile("cp.async.commit_group;");
    }

    for (int k = 0; k < NCH; ++k) {
        if (k + 1 < NCH) {
            int gcn = (int)(s_chk[k + 2] - s_chk[k + 1]);
            if (gcn <= RING_G)
                cp_chunk(ring[(k + 1) & 1], ws + (size_t)s_chk[k + 1] * 24,
                         gcn * 96, lane);
            asm volatile("cp.async.commit_group;");
            asm volatile("cp.async.wait_group 1;");
        } else {
            asm volatile("cp.async.wait_group 0;");
        }
        __syncwarp();

        const int myg = (int)(s_chk[k + 1] - s_chk[k]);
        const float* rb = (myg <= RING_G) ? (const float*)ring[k & 1]
                                          : (ws + (size_t)s_chk[k] * 24);
        if (lane < DOUT) {
            int gbase = 0;
            for (int e0 = 0; e0 < CEVT; ++e0) {
                const int e = k * CEVT + e0;
                h2 = __fmul_rn(h2, s_d2[e]);
                int m = s_gc[e];
                #pragma unroll 2
                for (int g = 0; g < m; ++g) {
                    float w0 = rb[(gbase + g) * 24 + lane];
                    float w1 = rb[(gbase + g) * 24 + 12 + lane];
                    h2 = __fadd_rn(h2, w0);
                    if (h2 >= 0.5f) { cnt += 1.0f; h2 = 0.0f; }
                    h2 = __fadd_rn(h2, w1);
                    if (h2 >= 0.5f) { cnt += 1.0f; h2 = 0.0f; }
                }
                gbase += m;
            }
        }
        __syncwarp();
    }

    if (lane < DOUT)
        out[b * DOUT + lane] = __fdiv_rn(cnt, 64.0f);
}

extern "C" void kernel_launch(void* const* d_in, const int* in_sizes, int n_in,
                              void* d_out, int out_size) {
    const float* times = (const float*)d_in[0];  // [256,1024] f32
    const int*   pixv  = (const int*)d_in[1];    // [256,1024] i32
    const float* W1    = (const float*)d_in[2];  // [400,784]
    const float* b1    = (const float*)d_in[3];  // [400]
    const float* W2    = (const float*)d_in[4];  // [10,400]
    const float* b2    = (const float*)d_in[5];  // [10]

    cudaFuncSetAttribute(l1_kernel,
                         cudaFuncAttributeMaxDynamicSharedMemorySize, A_SMEM);

    int prep_n = DIN * DH + DH * 12;
    prep_kernel<<<(prep_n + 255) / 256, 256>>>(W1, W2, b2);
    l1_kernel<<<BB, NT_A, A_SMEM>>>(times, pixv, b1);
    l2_kernel<<<BB, 32>>>(times, (float*)d_out);
}

// round 7
// speedup vs baseline: 3.3310x; 1.7701x over previous
#include <cuda_runtime.h>
#include <cuda_bf16.h>

#define EE 1024
#define BB 256
#define DIN 784
#define DH 400
#define DOUT 10
#define NT_A 416
#define PF 4
#define CAP_E 32768        // stream entries per sample (expected ~7000)
#define CEVT 64            // entries per l2 chunk

// Static device scratch (no cudaMalloc allowed)
__device__ float g_W1T[DIN * DH + 32];             // transposed W1 (+pad)
__device__ float g_W2r[(DH + 1) * DOUT];           // [401][10], row 400 = 0
__device__ float g_ms[(size_t)BB * CAP_E];         // stream: multiplier
__device__ unsigned short g_js[(size_t)BB * CAP_E];// stream: weight-row index
__device__ unsigned g_tot[BB];                     // padded stream length (or ~0 = overflow)
__device__ unsigned g_maskov[BB][EE][13];          // masks (overflow fallback only)

__global__ void prep_kernel(const float* __restrict__ W1,
                            const float* __restrict__ W2,
                            const float* __restrict__ b2) {
    int idx = blockIdx.x * blockDim.x + threadIdx.x;
    if (idx < DIN * DH) {
        int p = idx / DH;
        int j = idx - p * DH;
        g_W1T[idx] = W1[j * DIN + p];
    } else if (idx < DIN * DH + (DH + 1) * DOUT) {
        int i = idx - DIN * DH;
        int j = i / DOUT;
        int d = i - j * DOUT;
        g_W2r[i] = (j < DH)
            ? __fadd_rn(W2[d * DH + j], __fdiv_rn(b2[d], 400.0f))
            : 0.0f;
    }
}

#define A_SMEM ((EE + PF) * 8 + EE * 13 * 4 + EE * 4 * 3 + 32)

// Layer 1: one CTA/sample, 13 warps, depth-4 register prefetch, no barriers
// in main loop. Epilogue emits the uniform (m, j) FFMA stream.
__global__ __launch_bounds__(NT_A, 2) void l1_kernel(
    const float* __restrict__ times,
    const int*   __restrict__ pix,
    const float* __restrict__ b1)
{
    extern __shared__ unsigned char dyn[];
    float2*   s_ev   = (float2*)dyn;                   // [EE+PF] (decay1, byteoff)
    unsigned* s_mask = (unsigned*)(s_ev + EE + PF);    // [EE][13]
    float*    s_d2   = (float*)(s_mask + EE * 13);     // [EE]
    unsigned* s_ent  = (unsigned*)(s_d2 + EE);         // [EE] entries per event
    unsigned* s_off  = s_ent + EE;                     // [EE] exclusive prefix
    unsigned* s_T    = s_off + EE;                     // [1]

    const float TAUF = 0.6213349345596119f;  // float(-1/ln(0.2))
    const int b    = blockIdx.x;
    const int tid  = threadIdx.x;
    const int warp = tid >> 5;
    const int lane = tid & 31;

    for (int e = tid; e < EE; e += NT_A) {
        float t  = times[b * EE + e];
        float tp = (e > 0) ? times[b * EE + e - 1] : 0.0f;
        float d1 = expf(__fdiv_rn(-(t - tp), TAUF));
        float th  = __fadd_rn(t, 0.1f);
        float thp = (e > 0) ? __fadd_rn(tp, 0.1f) : 0.0f;
        s_d2[e] = expf(__fdiv_rn(-(th - thp), TAUF));
        int p = pix[b * EE + e];
        s_ev[e] = make_float2(d1, __int_as_float(p * (DH * 4)));
    }
    if (tid < PF) s_ev[EE + tid] = make_float2(1.0f, __int_as_float(0));
    __syncthreads();

    const bool valid = (tid < DH);
    float h1 = 0.0f;
    float bias1j = valid ? __fdiv_rn(b1[tid], 784.0f) : 0.0f;
    const char* w1b = (const char*)g_W1T + tid * 4;

    float wbuf[PF], dbuf[PF];
    #pragma unroll
    for (int i = 0; i < PF; ++i) {
        float2 ev = s_ev[i];
        dbuf[i] = ev.x;
        wbuf[i] = *(const float*)(w1b + __float_as_int(ev.y));
    }

    for (int e = 0; e < EE; e += PF) {
        #pragma unroll
        for (int u = 0; u < PF; ++u) {
            float2 evn = s_ev[e + u + PF];
            float d = dbuf[u], w = wbuf[u];
            dbuf[u] = evn.x;
            wbuf[u] = *(const float*)(w1b + __float_as_int(evn.y));

            h1 = __fadd_rn(__fadd_rn(__fmul_rn(h1, d), w), bias1j);
            bool fired = valid && (h1 >= 0.5f);
            h1 = fired ? 0.0f : h1;
            unsigned m = __ballot_sync(0xffffffffu, fired);
            if (lane == 0) s_mask[(e + u) * 13 + warp] = m;
        }
    }
    __syncthreads();

    // entries per event = 1 (decay) + n_spikes
    for (int e = tid; e < EE; e += NT_A) {
        int n = 0;
        #pragma unroll
        for (int w = 0; w < 13; ++w) n += __popc(s_mask[e * 13 + w]);
        s_ent[e] = (unsigned)(1 + n);
    }
    __syncthreads();

    // exclusive prefix scan (warp 0)
    if (warp == 0) {
        unsigned run = 0;
        for (int c = 0; c < EE / 32; ++c) {
            unsigned v = s_ent[c * 32 + lane];
            unsigned sc = v;
            #pragma unroll
            for (int d = 1; d < 32; d <<= 1) {
                unsigned u = __shfl_up_sync(0xffffffffu, sc, d);
                if (lane >= d) sc += u;
            }
            s_off[c * 32 + lane] = run + sc - v;
            run += __shfl_sync(0xffffffffu, sc, 31);
        }
        if (lane == 0) *s_T = run;
    }
    __syncthreads();

    const unsigned T = *s_T;
    const unsigned Tp = (T + (CEVT - 1)) & ~(unsigned)(CEVT - 1);

    if (Tp > CAP_E) {  // effectively never
        for (int i = tid; i < EE * 13; i += NT_A)
            (&g_maskov[b][0][0])[i] = s_mask[i];
        if (tid == 0) g_tot[b] = 0xFFFFFFFFu;
        return;
    }

    float* ms = g_ms + (size_t)b * CAP_E;
    unsigned short* js = g_js + (size_t)b * CAP_E;

    for (int e = warp; e < EE; e += 13) {
        unsigned off = s_off[e];
        if (lane == 0) { ms[off] = s_d2[e]; js[off] = (unsigned short)DH; }
        unsigned m = (lane < 13) ? s_mask[e * 13 + lane] : 0u;
        int c = __popc(m);
        int sc = c;
        #pragma unroll
        for (int d = 1; d < 32; d <<= 1) {
            int v = __shfl_up_sync(0xffffffffu, sc, d);
            if (lane >= d) sc += v;
        }
        int pos = sc - c;
        unsigned base = off + 1;
        while (m) {
            int bit = __ffs(m) - 1;
            m &= m - 1;
            ms[base + pos] = 1.0f;
            js[base + pos] = (unsigned short)(lane * 32 + bit);
            ++pos;
        }
    }
    // identity padding to chunk multiple
    for (unsigned i = T + tid; i < Tp; i += NT_A) {
        ms[i] = 1.0f;
        js[i] = (unsigned short)DH;
    }
    if (tid == 0) g_tot[b] = Tp;
}

// Layer 2: one warp per sample; lanes 0..9 run the uniform FFMA chain over
// the stream, cp.async-ring-buffered 4 chunks deep.
__global__ __launch_bounds__(32) void l2_kernel(
    const float* __restrict__ times,
    float*       __restrict__ out)
{
    __shared__ float s_W2p[(DH + 1) * DOUT];
    __shared__ __align__(16) float m_ring[4][CEVT];
    __shared__ __align__(16) unsigned short j_ring[4][CEVT];

    const int b    = blockIdx.x;
    const int lane = threadIdx.x;

    for (int i = lane; i < (DH + 1) * DOUT; i += 32) s_W2p[i] = g_W2r[i];
    const unsigned tot = g_tot[b];
    __syncwarp();

    float h2 = 0.0f, cnt = 0.0f;

    if (tot == 0xFFFFFFFFu) {
        // rare fallback: direct mask scan
        const float TAUF = 0.6213349345596119f;
        if (lane < DOUT) {
            for (int e = 0; e < EE; ++e) {
                float t   = times[b * EE + e];
                float tp  = (e > 0) ? times[b * EE + e - 1] : 0.0f;
                float th  = __fadd_rn(t, 0.1f);
                float thp = (e > 0) ? __fadd_rn(tp, 0.1f) : 0.0f;
                h2 = __fmul_rn(h2, expf(__fdiv_rn(-(th - thp), TAUF)));
                for (int w = 0; w < 13; ++w) {
                    unsigned m = g_maskov[b][e][w];
                    while (m) {
                        int bit = __ffs(m) - 1;
                        m &= m - 1;
                        int j = w * 32 + bit;
                        h2 = __fadd_rn(h2, s_W2p[j * DOUT + lane]);
                        if (h2 >= 0.5f) { cnt = __fadd_rn(cnt, 1.0f); h2 = 0.0f; }
                    }
                }
            }
            out[b * DOUT + lane] = __fdiv_rn(cnt, 64.0f);
        }
        return;
    }

    const float* ms = g_ms + (size_t)b * CAP_E;
    const unsigned short* js = g_js + (size_t)b * CAP_E;
    const int NC = (int)(tot / CEVT);   // >= 16 always

    // issue one chunk's cp.asyncs (lanes 0-15: m 256B, lanes 16-23: j 128B)
    auto issue = [&](int c) {
        int rb = c & 3;
        if (lane < 16) {
            unsigned dst = (unsigned)__cvta_generic_to_shared(&m_ring[rb][0]) + lane * 16;
            const char* src = (const char*)(ms + c * CEVT) + lane * 16;
            asm volatile("cp.async.ca.shared.global [%0], [%1], 16;" :: "r"(dst), "l"(src));
        } else if (lane < 24) {
            unsigned dst = (unsigned)__cvta_generic_to_shared(&j_ring[rb][0]) + (lane - 16) * 16;
            const char* src = (const char*)(js + c * CEVT) + (lane - 16) * 16;
            asm volatile("cp.async.ca.shared.global [%0], [%1], 16;" :: "r"(dst), "l"(src));
        }
        asm volatile("cp.async.commit_group;");
    };

    issue(0); issue(1); issue(2);

    for (int c = 0; c < NC; ++c) {
        asm volatile("cp.async.wait_group 2;");
        __syncwarp();
        if (lane < DOUT) {
            const int rb = c & 3;
            for (int i = 0; i < CEVT; i += 16) {
                #pragma unroll
                for (int u = 0; u < 16; ++u) {
                    float m = m_ring[rb][i + u];
                    int   j = j_ring[rb][i + u];
                    float w = s_W2p[j * DOUT + lane];
                    h2 = __fmaf_rn(h2, m, w);       // == FMUL (a=0) / FADD (m=1)
                    bool f = h2 >= 0.5f;
                    cnt = f ? __fadd_rn(cnt, 1.0f) : cnt;
                    h2 = f ? 0.0f : h2;
                }
            }
        }
        __syncwarp();
        if (c + 3 < NC) issue(c + 3);
        else asm volatile("cp.async.commit_group;");  // keep group counts uniform
    }

    if (lane < DOUT)
        out[b * DOUT + lane] = __fdiv_rn(cnt, 64.0f);
}

extern "C" void kernel_launch(void* const* d_in, const int* in_sizes, int n_in,
                              void* d_out, int out_size) {
    const float* times = (const float*)d_in[0];  // [256,1024] f32
    const int*   pixv  = (const int*)d_in[1];    // [256,1024] i32
    const float* W1    = (const float*)d_in[2];  // [400,784]
    const float* b1    = (const float*)d_in[3];  // [400]
    const float* W2    = (const float*)d_in[4];  // [10,400]
    const float* b2    = (const float*)d_in[5];  // [10]

    cudaFuncSetAttribute(l1_kernel,
                         cudaFuncAttributeMaxDynamicSharedMemorySize, A_SMEM);

    int prep_n = DIN * DH + (DH + 1) * DOUT;
    prep_kernel<<<(prep_n + 255) / 256, 256>>>(W1, W2, b2);
    l1_kernel<<<BB, NT_A, A_SMEM>>>(times, pixv, b1);
    l2_kernel<<<BB, 32>>>(times, (float*)d_out);
}

// round 8
// speedup vs baseline: 3.3372x; 1.0019x over previous
#include <cuda_runtime.h>
#include <cuda_bf16.h>

#define EE 1024
#define BB 256
#define DIN 784
#define DH 400
#define DOUT 10
#define NT_A 416
#define PF 4
#define CAP_E 32768        // stream entries per sample (expected ~7000)
#define CEVT 64            // entries per l2 chunk

// Static device scratch (no cudaMalloc allowed)
__device__ float g_W1T[DIN * DH + 32];             // transposed W1 (+pad)
__device__ float g_W2r[(DH + 1) * DOUT];           // [401][10], row 400 = 0
__device__ float g_ms[(size_t)BB * CAP_E];         // stream: multiplier
__device__ unsigned short g_js[(size_t)BB * CAP_E];// stream: weight-row index
__device__ unsigned g_tot[BB];                     // padded stream length (or ~0 = overflow)
__device__ unsigned g_maskov[BB][EE][13];          // masks (overflow fallback only)

__global__ void prep_kernel(const float* __restrict__ W1,
                            const float* __restrict__ W2,
                            const float* __restrict__ b2) {
    int idx = blockIdx.x * blockDim.x + threadIdx.x;
    if (idx < DIN * DH) {
        int p = idx / DH;
        int j = idx - p * DH;
        g_W1T[idx] = W1[j * DIN + p];
    } else if (idx < DIN * DH + (DH + 1) * DOUT) {
        int i = idx - DIN * DH;
        int j = i / DOUT;
        int d = i - j * DOUT;
        g_W2r[i] = (j < DH)
            ? __fadd_rn(W2[d * DH + j], __fdiv_rn(b2[d], 400.0f))
            : 0.0f;
    }
}

#define A_SMEM ((EE + PF) * 8 + EE * 13 * 4 + EE * 4 * 3 + 32)

// Layer 1: one CTA/sample, 13 warps, depth-4 register prefetch, no barriers
// in main loop. Epilogue emits the uniform (m, j) FFMA stream.
__global__ __launch_bounds__(NT_A, 2) void l1_kernel(
    const float* __restrict__ times,
    const int*   __restrict__ pix,
    const float* __restrict__ b1)
{
    extern __shared__ unsigned char dyn[];
    float2*   s_ev   = (float2*)dyn;                   // [EE+PF] (decay1, byteoff)
    unsigned* s_mask = (unsigned*)(s_ev + EE + PF);    // [EE][13]
    float*    s_d2   = (float*)(s_mask + EE * 13);     // [EE]
    unsigned* s_ent  = (unsigned*)(s_d2 + EE);         // [EE] entries per event
    unsigned* s_off  = s_ent + EE;                     // [EE] exclusive prefix
    unsigned* s_T    = s_off + EE;                     // [1]

    const float TAUF = 0.6213349345596119f;  // float(-1/ln(0.2))
    const int b    = blockIdx.x;
    const int tid  = threadIdx.x;
    const int warp = tid >> 5;
    const int lane = tid & 31;

    for (int e = tid; e < EE; e += NT_A) {
        float t  = times[b * EE + e];
        float tp = (e > 0) ? times[b * EE + e - 1] : 0.0f;
        float d1 = expf(__fdiv_rn(-(t - tp), TAUF));
        float th  = __fadd_rn(t, 0.1f);
        float thp = (e > 0) ? __fadd_rn(tp, 0.1f) : 0.0f;
        s_d2[e] = expf(__fdiv_rn(-(th - thp), TAUF));
        int p = pix[b * EE + e];
        s_ev[e] = make_float2(d1, __int_as_float(p * (DH * 4)));
    }
    if (tid < PF) s_ev[EE + tid] = make_float2(1.0f, __int_as_float(0));
    __syncthreads();

    const bool valid = (tid < DH);
    float h1 = 0.0f;
    float bias1j = valid ? __fdiv_rn(b1[tid], 784.0f) : 0.0f;
    const char* w1b = (const char*)g_W1T + tid * 4;

    float wbuf[PF], dbuf[PF];
    #pragma unroll
    for (int i = 0; i < PF; ++i) {
        float2 ev = s_ev[i];
        dbuf[i] = ev.x;
        wbuf[i] = *(const float*)(w1b + __float_as_int(ev.y));
    }

    for (int e = 0; e < EE; e += PF) {
        #pragma unroll
        for (int u = 0; u < PF; ++u) {
            float2 evn = s_ev[e + u + PF];
            float d = dbuf[u], w = wbuf[u];
            dbuf[u] = evn.x;
            wbuf[u] = *(const float*)(w1b + __float_as_int(evn.y));

            h1 = __fadd_rn(__fadd_rn(__fmul_rn(h1, d), w), bias1j);
            bool fired = valid && (h1 >= 0.5f);
            h1 = fired ? 0.0f : h1;
            unsigned m = __ballot_sync(0xffffffffu, fired);
            if (lane == 0) s_mask[(e + u) * 13 + warp] = m;
        }
    }
    __syncthreads();

    // entries per event = 1 (decay) + n_spikes
    for (int e = tid; e < EE; e += NT_A) {
        int n = 0;
        #pragma unroll
        for (int w = 0; w < 13; ++w) n += __popc(s_mask[e * 13 + w]);
        s_ent[e] = (unsigned)(1 + n);
    }
    __syncthreads();

    // exclusive prefix scan (warp 0)
    if (warp == 0) {
        unsigned run = 0;
        for (int c = 0; c < EE / 32; ++c) {
            unsigned v = s_ent[c * 32 + lane];
            unsigned sc = v;
            #pragma unroll
            for (int d = 1; d < 32; d <<= 1) {
                unsigned u = __shfl_up_sync(0xffffffffu, sc, d);
                if (lane >= d) sc += u;
            }
            s_off[c * 32 + lane] = run + sc - v;
            run += __shfl_sync(0xffffffffu, sc, 31);
        }
        if (lane == 0) *s_T = run;
    }
    __syncthreads();

    const unsigned T = *s_T;
    const unsigned Tp = (T + (CEVT - 1)) & ~(unsigned)(CEVT - 1);

    if (Tp > CAP_E) {  // effectively never
        for (int i = tid; i < EE * 13; i += NT_A)
            (&g_maskov[b][0][0])[i] = s_mask[i];
        if (tid == 0) g_tot[b] = 0xFFFFFFFFu;
        return;
    }

    float* ms = g_ms + (size_t)b * CAP_E;
    unsigned short* js = g_js + (size_t)b * CAP_E;

    for (int e = warp; e < EE; e += 13) {
        unsigned off = s_off[e];
        if (lane == 0) { ms[off] = s_d2[e]; js[off] = (unsigned short)DH; }
        unsigned m = (lane < 13) ? s_mask[e * 13 + lane] : 0u;
        int c = __popc(m);
        int sc = c;
        #pragma unroll
        for (int d = 1; d < 32; d <<= 1) {
            int v = __shfl_up_sync(0xffffffffu, sc, d);
            if (lane >= d) sc += v;
        }
        int pos = sc - c;
        unsigned base = off + 1;
        while (m) {
            int bit = __ffs(m) - 1;
            m &= m - 1;
            ms[base + pos] = 1.0f;
            js[base + pos] = (unsigned short)(lane * 32 + bit);
            ++pos;
        }
    }
    // identity padding to chunk multiple
    for (unsigned i = T + tid; i < Tp; i += NT_A) {
        ms[i] = 1.0f;
        js[i] = (unsigned short)DH;
    }
    if (tid == 0) g_tot[b] = Tp;
}

// Layer 2: one warp per sample; lanes 0..9 run the uniform FFMA chain over
// the stream, cp.async-ring-buffered 4 chunks deep.
__global__ __launch_bounds__(32) void l2_kernel(
    const float* __restrict__ times,
    float*       __restrict__ out)
{
    __shared__ float s_W2p[(DH + 1) * DOUT];
    __shared__ __align__(16) float m_ring[4][CEVT];
    __shared__ __align__(16) unsigned short j_ring[4][CEVT];

    const int b    = blockIdx.x;
    const int lane = threadIdx.x;

    for (int i = lane; i < (DH + 1) * DOUT; i += 32) s_W2p[i] = g_W2r[i];
    const unsigned tot = g_tot[b];
    __syncwarp();

    float h2 = 0.0f, cnt = 0.0f;

    if (tot == 0xFFFFFFFFu) {
        // rare fallback: direct mask scan
        const float TAUF = 0.6213349345596119f;
        if (lane < DOUT) {
            for (int e = 0; e < EE; ++e) {
                float t   = times[b * EE + e];
                float tp  = (e > 0) ? times[b * EE + e - 1] : 0.0f;
                float th  = __fadd_rn(t, 0.1f);
                float thp = (e > 0) ? __fadd_rn(tp, 0.1f) : 0.0f;
                h2 = __fmul_rn(h2, expf(__fdiv_rn(-(th - thp), TAUF)));
                for (int w = 0; w < 13; ++w) {
                    unsigned m = g_maskov[b][e][w];
                    while (m) {
                        int bit = __ffs(m) - 1;
                        m &= m - 1;
                        int j = w * 32 + bit;
                        h2 = __fadd_rn(h2, s_W2p[j * DOUT + lane]);
                        if (h2 >= 0.5f) { cnt = __fadd_rn(cnt, 1.0f); h2 = 0.0f; }
                    }
                }
            }
            out[b * DOUT + lane] = __fdiv_rn(cnt, 64.0f);
        }
        return;
    }

    const float* ms = g_ms + (size_t)b * CAP_E;
    const unsigned short* js = g_js + (size_t)b * CAP_E;
    const int NC = (int)(tot / CEVT);   // >= 16 always

    // issue one chunk's cp.asyncs (lanes 0-15: m 256B, lanes 16-23: j 128B)
    auto issue = [&](int c) {
        int rb = c & 3;
        if (lane < 16) {
            unsigned dst = (unsigned)__cvta_generic_to_shared(&m_ring[rb][0]) + lane * 16;
            const char* src = (const char*)(ms + c * CEVT) + lane * 16;
            asm volatile("cp.async.ca.shared.global [%0], [%1], 16;" :: "r"(dst), "l"(src));
        } else if (lane < 24) {
            unsigned dst = (unsigned)__cvta_generic_to_shared(&j_ring[rb][0]) + (lane - 16) * 16;
            const char* src = (const char*)(js + c * CEVT) + (lane - 16) * 16;
            asm volatile("cp.async.ca.shared.global [%0], [%1], 16;" :: "r"(dst), "l"(src));
        }
        asm volatile("cp.async.commit_group;");
    };

    issue(0); issue(1); issue(2);

    for (int c = 0; c < NC; ++c) {
        asm volatile("cp.async.wait_group 2;");
        __syncwarp();
        if (lane < DOUT) {
            const int rb = c & 3;
            for (int i = 0; i < CEVT; i += 16) {
                #pragma unroll
                for (int u = 0; u < 16; ++u) {
                    float m = m_ring[rb][i + u];
                    int   j = j_ring[rb][i + u];
                    float w = s_W2p[j * DOUT + lane];
                    h2 = __fmaf_rn(h2, m, w);       // == FMUL (a=0) / FADD (m=1)
                    bool f = h2 >= 0.5f;
                    cnt = f ? __fadd_rn(cnt, 1.0f) : cnt;
                    h2 = f ? 0.0f : h2;
                }
            }
        }
        __syncwarp();
        if (c + 3 < NC) issue(c + 3);
        else asm volatile("cp.async.commit_group;");  // keep group counts uniform
    }

    if (lane < DOUT)
        out[b * DOUT + lane] = __fdiv_rn(cnt, 64.0f);
}

extern "C" void kernel_launch(void* const* d_in, const int* in_sizes, int n_in,
                              void* d_out, int out_size) {
    const float* times = (const float*)d_in[0];  // [256,1024] f32
    const int*   pixv  = (const int*)d_in[1];    // [256,1024] i32
    const float* W1    = (const float*)d_in[2];  // [400,784]
    const float* b1    = (const float*)d_in[3];  // [400]
    const float* W2    = (const float*)d_in[4];  // [10,400]
    const float* b2    = (const float*)d_in[5];  // [10]

    cudaFuncSetAttribute(l1_kernel,
                         cudaFuncAttributeMaxDynamicSharedMemorySize, A_SMEM);

    int prep_n = DIN * DH + (DH + 1) * DOUT;
    prep_kernel<<<(prep_n + 255) / 256, 256>>>(W1, W2, b2);
    l1_kernel<<<BB, NT_A, A_SMEM>>>(times, pixv, b1);
    l2_kernel<<<BB, 32>>>(times, (float*)d_out);
}